// round 15
// baseline (speedup 1.0000x reference)
#include <cuda_runtime.h>
#include <math.h>

// Problem constants
#define HH     8192
#define IDIM   4096
#define ODIM   4096
#define NTOT   (HH + ODIM)      // 12288
#define NSTEPS 100
#define MAXROWS 64              // max rows any block can own (grid >= 152)

// Scratch (no allocations allowed)
__device__ __align__(128) float g_Ihid[HH];   // compress(W1 @ v_input)
__device__ __align__(128) float g_Iout[ODIM]; // compress(W2 @ I_hidden)

// Grid barrier state (sense-reversal; safe across graph replays).
__device__ unsigned g_bar_cnt = 0;
__device__ volatile unsigned g_bar_gen = 0;

__device__ __forceinline__ void grid_barrier() {
    __syncthreads();
    if (threadIdx.x == 0) {
        unsigned gen = g_bar_gen;           // read phase BEFORE arriving
        __threadfence();                    // publish this block's writes
        if (atomicAdd(&g_bar_cnt, 1u) == gridDim.x - 1u) {
            g_bar_cnt = 0;
            __threadfence();
            g_bar_gen = gen + 1u;           // release
        } else {
            while (g_bar_gen == gen) { }
        }
    }
    __syncthreads();
}

__device__ __forceinline__ float compress_fn(float x, float gain) {
    float s = (x > 0.0f) ? 1.0f : ((x < 0.0f) ? -1.0f : 0.0f);
    return s * log1pf(gain * fabsf(x) + 1e-6f);
}

__device__ __forceinline__ int range_pt(int b, int G, int R) {
    return (int)(((long long)b * R) / G);
}

// 4-row dot: 256 threads, thread t handles idx = k*256+t, elements .x.y.z.w.
// Per-row FMA ordering identical to all passing kernels. Weight loads use
// __ldcs (streaming, evict-first): weights are single-touch, keep L2 for x.
template <int NCOLS>
__device__ __forceinline__ void rows4_dot(const float* __restrict__ W,
                                          const float* __restrict__ x,
                                          int row0,
                                          float& a0, float& a1, float& a2, float& a3) {
    const float4* xv = reinterpret_cast<const float4*>(x);
    const float4* w0 = reinterpret_cast<const float4*>(W + (size_t)(row0 + 0) * NCOLS);
    const float4* w1 = reinterpret_cast<const float4*>(W + (size_t)(row0 + 1) * NCOLS);
    const float4* w2 = reinterpret_cast<const float4*>(W + (size_t)(row0 + 2) * NCOLS);
    const float4* w3 = reinterpret_cast<const float4*>(W + (size_t)(row0 + 3) * NCOLS);
    constexpr int PER = NCOLS / 4 / 256;
    a0 = a1 = a2 = a3 = 0.0f;
    #pragma unroll
    for (int k = 0; k < PER; ++k) {
        int idx = k * 256 + threadIdx.x;
        float4 xx = xv[idx];
        float4 r0 = __ldcs(w0 + idx);
        float4 r1 = __ldcs(w1 + idx);
        float4 r2 = __ldcs(w2 + idx);
        float4 r3 = __ldcs(w3 + idx);
        a0 = fmaf(r0.x, xx.x, a0); a0 = fmaf(r0.y, xx.y, a0);
        a0 = fmaf(r0.z, xx.z, a0); a0 = fmaf(r0.w, xx.w, a0);
        a1 = fmaf(r1.x, xx.x, a1); a1 = fmaf(r1.y, xx.y, a1);
        a1 = fmaf(r1.z, xx.z, a1); a1 = fmaf(r1.w, xx.w, a1);
        a2 = fmaf(r2.x, xx.x, a2); a2 = fmaf(r2.y, xx.y, a2);
        a2 = fmaf(r2.z, xx.z, a2); a2 = fmaf(r2.w, xx.w, a2);
        a3 = fmaf(r3.x, xx.x, a3); a3 = fmaf(r3.y, xx.y, a3);
        a3 = fmaf(r3.z, xx.z, a3); a3 = fmaf(r3.w, xx.w, a3);
    }
}

// Single-row dot, same per-thread/index ordering.
template <int NCOLS>
__device__ __forceinline__ float row1_dot(const float* __restrict__ W,
                                          const float* __restrict__ x, int row) {
    const float4* xv = reinterpret_cast<const float4*>(x);
    const float4* wr = reinterpret_cast<const float4*>(W + (size_t)row * NCOLS);
    constexpr int PER = NCOLS / 4 / 256;
    float a = 0.0f;
    #pragma unroll
    for (int k = 0; k < PER; ++k) {
        int idx = k * 256 + threadIdx.x;
        float4 xx = xv[idx];
        float4 ww = __ldcs(wr + idx);
        a = fmaf(ww.x, xx.x, a); a = fmaf(ww.y, xx.y, a);
        a = fmaf(ww.z, xx.z, a); a = fmaf(ww.w, xx.w, a);
    }
    return a;
}

// Block reduce of 4 sums, 256 threads. Same xor tree as passing kernels.
__device__ __forceinline__ void block_reduce4(float& a0, float& a1, float& a2, float& a3) {
    __shared__ float s[8][4];
    __syncthreads();
    #pragma unroll
    for (int o = 16; o > 0; o >>= 1) {
        a0 += __shfl_xor_sync(0xffffffffu, a0, o);
        a1 += __shfl_xor_sync(0xffffffffu, a1, o);
        a2 += __shfl_xor_sync(0xffffffffu, a2, o);
        a3 += __shfl_xor_sync(0xffffffffu, a3, o);
    }
    if ((threadIdx.x & 31) == 0) {
        int w = threadIdx.x >> 5;
        s[w][0] = a0; s[w][1] = a1; s[w][2] = a2; s[w][3] = a3;
    }
    __syncthreads();
    if (threadIdx.x < 32) {
        bool in = threadIdx.x < 8;
        a0 = in ? s[threadIdx.x][0] : 0.0f;
        a1 = in ? s[threadIdx.x][1] : 0.0f;
        a2 = in ? s[threadIdx.x][2] : 0.0f;
        a3 = in ? s[threadIdx.x][3] : 0.0f;
        #pragma unroll
        for (int o = 4; o > 0; o >>= 1) {
            a0 += __shfl_xor_sync(0xffffffffu, a0, o);
            a1 += __shfl_xor_sync(0xffffffffu, a1, o);
            a2 += __shfl_xor_sync(0xffffffffu, a2, o);
            a3 += __shfl_xor_sync(0xffffffffu, a3, o);
        }
    }
}

// Block reduce of 1 sum (identical to R7's proven tree).
__device__ __forceinline__ float block_reduce1(float val) {
    __shared__ float s1[8];
    __syncthreads();
    #pragma unroll
    for (int o = 16; o > 0; o >>= 1)
        val += __shfl_xor_sync(0xffffffffu, val, o);
    if ((threadIdx.x & 31) == 0) s1[threadIdx.x >> 5] = val;
    __syncthreads();
    if (threadIdx.x < 32) {
        val = (threadIdx.x < 8) ? s1[threadIdx.x] : 0.0f;
        #pragma unroll
        for (int o = 4; o > 0; o >>= 1)
            val += __shfl_xor_sync(0xffffffffu, val, o);
    }
    return val;
}

// 100-step Izhikevich trajectory for one neuron. Streaming stores (__stcs):
// trajectories are write-once, keep L2 for the x-vectors.
// Output layout: out[0]=loss, v at out[1 + t*NTOT + n], u after all v.
__device__ __forceinline__ void izhi_run(int n, float Iin, float* __restrict__ out) {
    float* vp = out + 1 + n;
    float* up = out + 1 + (size_t)NSTEPS * NTOT + n;
    float v = -65.0f;
    float u = 0.2f * -65.0f;   // -13
    __stcs(vp, v); __stcs(up, u);
    #pragma unroll 4
    for (int t = 1; t < NSTEPS; ++t) {
        vp += NTOT; up += NTOT;
        float vn = v + (0.04f * v * v + 5.0f * v + 0.14f - u + Iin);
        float un = u + 0.02f * (0.2f * v - u);
        bool sp = (vn >= 30.0f);
        v = sp ? -65.0f : vn;
        u = sp ? (un + 8.0f) : un;
        __stcs(vp, v); __stcs(up, u);
    }
}

// Persistent kernel, all blocks co-resident. Static contiguous row ranges.
// launch_bounds(256, 6): cap regs at 42 so 6 blocks/SM fit (48 warps, 75% occ)
// — streaming rate tracks resident warps; the hot dot loop fit 38 regs in R10.
__global__ void __launch_bounds__(256, 6) k_fused(
    const float* __restrict__ vin,   const float* __restrict__ target,
    const float* __restrict__ W1,    const float* __restrict__ W2,
    const float* __restrict__ Wfb,   const float* __restrict__ gain1,
    const float* __restrict__ gain2, float* __restrict__ out)
{
    const int G = gridDim.x;
    const int b = blockIdx.x;

    // ---- Phase 1: g_Ihid = compress(W1 @ v_input, gain1) ----
    {
        int r0 = range_pt(b, G, HH), r1 = range_pt(b + 1, G, HH);
        int r = r0;
        for (; r + 4 <= r1; r += 4) {
            float a0, a1, a2, a3;
            rows4_dot<IDIM>(W1, vin, r, a0, a1, a2, a3);
            block_reduce4(a0, a1, a2, a3);
            if (threadIdx.x == 0) {
                float gn = gain1[0];
                g_Ihid[r + 0] = compress_fn(a0, gn);
                g_Ihid[r + 1] = compress_fn(a1, gn);
                g_Ihid[r + 2] = compress_fn(a2, gn);
                g_Ihid[r + 3] = compress_fn(a3, gn);
            }
        }
        for (; r < r1; ++r) {
            float a = row1_dot<IDIM>(W1, vin, r);
            a = block_reduce1(a);
            if (threadIdx.x == 0)
                g_Ihid[r] = compress_fn(a, gain1[0]);
        }
    }
    grid_barrier();

    // ---- Phase 2: g_Iout = compress(W2 @ g_Ihid, gain2) ----
    {
        int r0 = range_pt(b, G, ODIM), r1 = range_pt(b + 1, G, ODIM);
        int r = r0;
        for (; r + 4 <= r1; r += 4) {
            float a0, a1, a2, a3;
            rows4_dot<HH>(W2, g_Ihid, r, a0, a1, a2, a3);
            block_reduce4(a0, a1, a2, a3);
            if (threadIdx.x == 0) {
                float gn = gain2[0];
                g_Iout[r + 0] = compress_fn(a0, gn);
                g_Iout[r + 1] = compress_fn(a1, gn);
                g_Iout[r + 2] = compress_fn(a2, gn);
                g_Iout[r + 3] = compress_fn(a3, gn);
            }
        }
        for (; r < r1; ++r) {
            float a = row1_dot<HH>(W2, g_Ihid, r);
            a = block_reduce1(a);
            if (threadIdx.x == 0)
                g_Iout[r] = compress_fn(a, gain2[0]);
        }
    }
    grid_barrier();

    // ---- Phase 3: total_hidden = g_Ihid - Wfb @ g_Iout (currents kept in
    //      smem), then in-block hidden izhi; blocks 0..15 add output izhi,
    //      block 16 the loss. No further barriers. ----
    __shared__ float cur[MAXROWS];
    {
        int r0 = range_pt(b, G, HH), r1 = range_pt(b + 1, G, HH);
        int r = r0;
        for (; r + 4 <= r1; r += 4) {
            float a0, a1, a2, a3;
            rows4_dot<ODIM>(Wfb, g_Iout, r, a0, a1, a2, a3);
            block_reduce4(a0, a1, a2, a3);
            if (threadIdx.x == 0) {
                int j = r - r0;
                cur[j + 0] = g_Ihid[r + 0] - a0;
                cur[j + 1] = g_Ihid[r + 1] - a1;
                cur[j + 2] = g_Ihid[r + 2] - a2;
                cur[j + 3] = g_Ihid[r + 3] - a3;
            }
        }
        for (; r < r1; ++r) {
            float a = row1_dot<ODIM>(Wfb, g_Iout, r);
            a = block_reduce1(a);
            if (threadIdx.x == 0)
                cur[r - r0] = g_Ihid[r] - a;
        }
        __syncthreads();

        // Hidden-neuron izhi for this block's own rows (contiguous lanes).
        int nrows = r1 - r0;
        if (threadIdx.x < nrows)
            izhi_run(r0 + threadIdx.x, cur[threadIdx.x], out);
    }

    // Output-neuron izhi: 16 blocks x 256 neurons (needs only g_Iout,
    // finalized at barrier 2).
    if (b < ODIM / 256) {
        int n = b * 256 + threadIdx.x;
        izhi_run(HH + n, g_Iout[n], out);
    } else if (b == ODIM / 256) {
        // loss = mean((I_output - target)^2)
        float acc = 0.0f;
        for (int i = threadIdx.x; i < ODIM; i += 256) {
            float d = g_Iout[i] - target[i];
            acc = fmaf(d, d, acc);
        }
        acc = block_reduce1(acc);
        if (threadIdx.x == 0)
            out[0] = acc / (float)ODIM;
    }
}

extern "C" void kernel_launch(void* const* d_in, const int* in_sizes, int n_in,
                              void* d_out, int out_size) {
    // metadata order: v_input, target_output, W1, W2, W_feedback, gain1, gain2
    const float* v_input = (const float*)d_in[0];
    const float* target  = (const float*)d_in[1];
    const float* W1      = (const float*)d_in[2];
    const float* W2      = (const float*)d_in[3];
    const float* Wfb     = (const float*)d_in[4];
    const float* gain1   = (const float*)d_in[5];
    const float* gain2   = (const float*)d_in[6];
    float* out = (float*)d_out;

    // 6 blocks/SM target, guaranteed co-resident (min with occupancy API —
    // spin barrier must not deadlock).
    int dev = 0;
    cudaGetDevice(&dev);
    int sm = 0;
    cudaDeviceGetAttribute(&sm, cudaDevAttrMultiProcessorCount, dev);
    int occ = 0;
    cudaOccupancyMaxActiveBlocksPerMultiprocessor(&occ, k_fused, 256, 0);
    if (sm < 1) sm = 1;
    int bps = (occ < 6) ? occ : 6;
    if (bps < 1) bps = 1;
    int grid = sm * bps;

    k_fused<<<grid, 256>>>(v_input, target, W1, W2, Wfb, gain1, gain2, out);
    (void)in_sizes; (void)n_in; (void)out_size;
}

// round 16
// speedup vs baseline: 1.0332x; 1.0332x over previous
#include <cuda_runtime.h>
#include <math.h>

// Problem constants
#define HH     8192
#define IDIM   4096
#define ODIM   4096
#define NTOT   (HH + ODIM)      // 12288
#define NSTEPS 100
#define MAXROWS 64              // max rows any block can own (grid >= 152)
#define NIZB   17               // blocks 0..15 output-izhi, 16 loss

// Scratch (no allocations allowed)
__device__ __align__(128) float g_Ihid[HH];   // compress(W1 @ v_input)
__device__ __align__(128) float g_Iout[ODIM]; // compress(W2 @ I_hidden)

// Grid barrier state (sense-reversal; safe across graph replays).
__device__ unsigned g_bar_cnt = 0;
__device__ volatile unsigned g_bar_gen = 0;

__device__ __forceinline__ void grid_barrier() {
    __syncthreads();
    if (threadIdx.x == 0) {
        unsigned gen = g_bar_gen;           // read phase BEFORE arriving
        __threadfence();                    // publish this block's writes
        if (atomicAdd(&g_bar_cnt, 1u) == gridDim.x - 1u) {
            g_bar_cnt = 0;
            __threadfence();
            g_bar_gen = gen + 1u;           // release
        } else {
            while (g_bar_gen == gen) { }
        }
    }
    __syncthreads();
}

__device__ __forceinline__ float compress_fn(float x, float gain) {
    float s = (x > 0.0f) ? 1.0f : ((x < 0.0f) ? -1.0f : 0.0f);
    return s * log1pf(gain * fabsf(x) + 1e-6f);
}

// Even split (phases 1 and 2).
__device__ __forceinline__ int range_pt(int b, int G, int R) {
    return (int)(((long long)b * R) / G);
}

// Weighted split for phase 3: blocks 0..NIZB-1 (which also run output-izhi /
// loss) carry weight 15, others 16 -> ~1 row less each, balancing the tail.
__device__ __forceinline__ int p3_row(int b, int G) {
    long long mb = (b < NIZB) ? b : NIZB;
    long long cum = 16LL * b - mb;
    long long total = 16LL * G - NIZB;
    return (int)(((long long)HH * cum) / total);
}

// 4-row dot, software-pipelined: prefetch next k-iteration's 4 weight float4s
// before the current FMAs. Per-row FMA ORDER is bit-identical to all passing
// kernels (thread t handles idx = k*256+t, elements .x.y.z.w, same accs).
template <int NCOLS>
__device__ __forceinline__ void rows4_dot(const float* __restrict__ W,
                                          const float* __restrict__ x,
                                          int row0,
                                          float& a0, float& a1, float& a2, float& a3) {
    const float4* xv = reinterpret_cast<const float4*>(x);
    const float4* w0 = reinterpret_cast<const float4*>(W + (size_t)(row0 + 0) * NCOLS);
    const float4* w1 = reinterpret_cast<const float4*>(W + (size_t)(row0 + 1) * NCOLS);
    const float4* w2 = reinterpret_cast<const float4*>(W + (size_t)(row0 + 2) * NCOLS);
    const float4* w3 = reinterpret_cast<const float4*>(W + (size_t)(row0 + 3) * NCOLS);
    constexpr int PER = NCOLS / 4 / 256;
    a0 = a1 = a2 = a3 = 0.0f;

    float4 n0 = w0[threadIdx.x];
    float4 n1 = w1[threadIdx.x];
    float4 n2 = w2[threadIdx.x];
    float4 n3 = w3[threadIdx.x];
    #pragma unroll
    for (int k = 0; k < PER; ++k) {
        float4 c0 = n0, c1 = n1, c2 = n2, c3 = n3;
        if (k + 1 < PER) {
            int nidx = (k + 1) * 256 + threadIdx.x;
            n0 = w0[nidx]; n1 = w1[nidx]; n2 = w2[nidx]; n3 = w3[nidx];
        }
        float4 xx = xv[k * 256 + threadIdx.x];
        a0 = fmaf(c0.x, xx.x, a0); a0 = fmaf(c0.y, xx.y, a0);
        a0 = fmaf(c0.z, xx.z, a0); a0 = fmaf(c0.w, xx.w, a0);
        a1 = fmaf(c1.x, xx.x, a1); a1 = fmaf(c1.y, xx.y, a1);
        a1 = fmaf(c1.z, xx.z, a1); a1 = fmaf(c1.w, xx.w, a1);
        a2 = fmaf(c2.x, xx.x, a2); a2 = fmaf(c2.y, xx.y, a2);
        a2 = fmaf(c2.z, xx.z, a2); a2 = fmaf(c2.w, xx.w, a2);
        a3 = fmaf(c3.x, xx.x, a3); a3 = fmaf(c3.y, xx.y, a3);
        a3 = fmaf(c3.z, xx.z, a3); a3 = fmaf(c3.w, xx.w, a3);
    }
}

// Single-row dot, same per-thread/index ordering as all passing kernels.
template <int NCOLS>
__device__ __forceinline__ float row1_dot(const float* __restrict__ W,
                                          const float* __restrict__ x, int row) {
    const float4* xv = reinterpret_cast<const float4*>(x);
    const float4* wr = reinterpret_cast<const float4*>(W + (size_t)row * NCOLS);
    constexpr int PER = NCOLS / 4 / 256;
    float a = 0.0f;
    #pragma unroll
    for (int k = 0; k < PER; ++k) {
        int idx = k * 256 + threadIdx.x;
        float4 xx = xv[idx];
        float4 ww = wr[idx];
        a = fmaf(ww.x, xx.x, a); a = fmaf(ww.y, xx.y, a);
        a = fmaf(ww.z, xx.z, a); a = fmaf(ww.w, xx.w, a);
    }
    return a;
}

// Block reduce of 4 sums, 256 threads. Same xor tree as passing kernels.
__device__ __forceinline__ void block_reduce4(float& a0, float& a1, float& a2, float& a3) {
    __shared__ float s[8][4];
    __syncthreads();
    #pragma unroll
    for (int o = 16; o > 0; o >>= 1) {
        a0 += __shfl_xor_sync(0xffffffffu, a0, o);
        a1 += __shfl_xor_sync(0xffffffffu, a1, o);
        a2 += __shfl_xor_sync(0xffffffffu, a2, o);
        a3 += __shfl_xor_sync(0xffffffffu, a3, o);
    }
    if ((threadIdx.x & 31) == 0) {
        int w = threadIdx.x >> 5;
        s[w][0] = a0; s[w][1] = a1; s[w][2] = a2; s[w][3] = a3;
    }
    __syncthreads();
    if (threadIdx.x < 32) {
        bool in = threadIdx.x < 8;
        a0 = in ? s[threadIdx.x][0] : 0.0f;
        a1 = in ? s[threadIdx.x][1] : 0.0f;
        a2 = in ? s[threadIdx.x][2] : 0.0f;
        a3 = in ? s[threadIdx.x][3] : 0.0f;
        #pragma unroll
        for (int o = 4; o > 0; o >>= 1) {
            a0 += __shfl_xor_sync(0xffffffffu, a0, o);
            a1 += __shfl_xor_sync(0xffffffffu, a1, o);
            a2 += __shfl_xor_sync(0xffffffffu, a2, o);
            a3 += __shfl_xor_sync(0xffffffffu, a3, o);
        }
    }
}

// Block reduce of 1 sum (identical to R7's proven tree).
__device__ __forceinline__ float block_reduce1(float val) {
    __shared__ float s1[8];
    __syncthreads();
    #pragma unroll
    for (int o = 16; o > 0; o >>= 1)
        val += __shfl_xor_sync(0xffffffffu, val, o);
    if ((threadIdx.x & 31) == 0) s1[threadIdx.x >> 5] = val;
    __syncthreads();
    if (threadIdx.x < 32) {
        val = (threadIdx.x < 8) ? s1[threadIdx.x] : 0.0f;
        #pragma unroll
        for (int o = 4; o > 0; o >>= 1)
            val += __shfl_xor_sync(0xffffffffu, val, o);
    }
    return val;
}

// 100-step Izhikevich trajectory for one neuron.
// Output layout: out[0]=loss, v at out[1 + t*NTOT + n], u after all v.
__device__ __forceinline__ void izhi_run(int n, float Iin, float* __restrict__ out) {
    float* vp = out + 1 + n;
    float* up = out + 1 + (size_t)NSTEPS * NTOT + n;
    float v = -65.0f;
    float u = 0.2f * -65.0f;   // -13
    *vp = v; *up = u;
    #pragma unroll 4
    for (int t = 1; t < NSTEPS; ++t) {
        vp += NTOT; up += NTOT;
        float vn = v + (0.04f * v * v + 5.0f * v + 0.14f - u + Iin);
        float un = u + 0.02f * (0.2f * v - u);
        bool sp = (vn >= 30.0f);
        v = sp ? -65.0f : vn;
        u = sp ? (un + 8.0f) : un;
        *vp = v; *up = u;
    }
}

// Persistent kernel, all blocks co-resident. Static contiguous row ranges.
// launch_bounds(256, 4): 64-reg budget — R13-proven best MLP configuration.
__global__ void __launch_bounds__(256, 4) k_fused(
    const float* __restrict__ vin,   const float* __restrict__ target,
    const float* __restrict__ W1,    const float* __restrict__ W2,
    const float* __restrict__ Wfb,   const float* __restrict__ gain1,
    const float* __restrict__ gain2, float* __restrict__ out)
{
    const int G = gridDim.x;
    const int b = blockIdx.x;

    // ---- Phase 1: g_Ihid = compress(W1 @ v_input, gain1) ----
    {
        int r0 = range_pt(b, G, HH), r1 = range_pt(b + 1, G, HH);
        int r = r0;
        for (; r + 4 <= r1; r += 4) {
            float a0, a1, a2, a3;
            rows4_dot<IDIM>(W1, vin, r, a0, a1, a2, a3);
            block_reduce4(a0, a1, a2, a3);
            if (threadIdx.x == 0) {
                float gn = gain1[0];
                g_Ihid[r + 0] = compress_fn(a0, gn);
                g_Ihid[r + 1] = compress_fn(a1, gn);
                g_Ihid[r + 2] = compress_fn(a2, gn);
                g_Ihid[r + 3] = compress_fn(a3, gn);
            }
        }
        for (; r < r1; ++r) {
            float a = row1_dot<IDIM>(W1, vin, r);
            a = block_reduce1(a);
            if (threadIdx.x == 0)
                g_Ihid[r] = compress_fn(a, gain1[0]);
        }
    }
    grid_barrier();

    // ---- Phase 2: g_Iout = compress(W2 @ g_Ihid, gain2) ----
    {
        int r0 = range_pt(b, G, ODIM), r1 = range_pt(b + 1, G, ODIM);
        int r = r0;
        for (; r + 4 <= r1; r += 4) {
            float a0, a1, a2, a3;
            rows4_dot<HH>(W2, g_Ihid, r, a0, a1, a2, a3);
            block_reduce4(a0, a1, a2, a3);
            if (threadIdx.x == 0) {
                float gn = gain2[0];
                g_Iout[r + 0] = compress_fn(a0, gn);
                g_Iout[r + 1] = compress_fn(a1, gn);
                g_Iout[r + 2] = compress_fn(a2, gn);
                g_Iout[r + 3] = compress_fn(a3, gn);
            }
        }
        for (; r < r1; ++r) {
            float a = row1_dot<HH>(W2, g_Ihid, r);
            a = block_reduce1(a);
            if (threadIdx.x == 0)
                g_Iout[r] = compress_fn(a, gain2[0]);
        }
    }
    grid_barrier();

    // ---- Phase 3: blocks 0..16 run output-izhi / loss FIRST (hidden under
    //      the other blocks' Wfb streaming), then everyone streams their
    //      (weighted) Wfb rows and runs in-block hidden izhi. ----
    if (b < NIZB - 1) {
        int n = b * 256 + threadIdx.x;      // 16 blocks x 256 = 4096 outputs
        izhi_run(HH + n, g_Iout[n], out);
    } else if (b == NIZB - 1) {
        // loss = mean((I_output - target)^2)
        float acc = 0.0f;
        for (int i = threadIdx.x; i < ODIM; i += 256) {
            float d = g_Iout[i] - target[i];
            acc = fmaf(d, d, acc);
        }
        acc = block_reduce1(acc);
        if (threadIdx.x == 0)
            out[0] = acc / (float)ODIM;
    }

    __shared__ float cur[MAXROWS];
    {
        int r0 = p3_row(b, G), r1 = p3_row(b + 1, G);
        int r = r0;
        for (; r + 4 <= r1; r += 4) {
            float a0, a1, a2, a3;
            rows4_dot<ODIM>(Wfb, g_Iout, r, a0, a1, a2, a3);
            block_reduce4(a0, a1, a2, a3);
            if (threadIdx.x == 0) {
                int j = r - r0;
                cur[j + 0] = g_Ihid[r + 0] - a0;
                cur[j + 1] = g_Ihid[r + 1] - a1;
                cur[j + 2] = g_Ihid[r + 2] - a2;
                cur[j + 3] = g_Ihid[r + 3] - a3;
            }
        }
        for (; r < r1; ++r) {
            float a = row1_dot<ODIM>(Wfb, g_Iout, r);
            a = block_reduce1(a);
            if (threadIdx.x == 0)
                cur[r - r0] = g_Ihid[r] - a;
        }
        __syncthreads();

        // Hidden-neuron izhi for this block's own rows (contiguous lanes).
        int nrows = r1 - r0;
        if (threadIdx.x < nrows)
            izhi_run(r0 + threadIdx.x, cur[threadIdx.x], out);
    }
}

extern "C" void kernel_launch(void* const* d_in, const int* in_sizes, int n_in,
                              void* d_out, int out_size) {
    // metadata order: v_input, target_output, W1, W2, W_feedback, gain1, gain2
    const float* v_input = (const float*)d_in[0];
    const float* target  = (const float*)d_in[1];
    const float* W1      = (const float*)d_in[2];
    const float* W2      = (const float*)d_in[3];
    const float* Wfb     = (const float*)d_in[4];
    const float* gain1   = (const float*)d_in[5];
    const float* gain2   = (const float*)d_in[6];
    float* out = (float*)d_out;

    // 4 blocks/SM, guaranteed co-resident (min with occupancy API — the spin
    // barrier must not deadlock).
    int dev = 0;
    cudaGetDevice(&dev);
    int sm = 0;
    cudaDeviceGetAttribute(&sm, cudaDevAttrMultiProcessorCount, dev);
    int occ = 0;
    cudaOccupancyMaxActiveBlocksPerMultiprocessor(&occ, k_fused, 256, 0);
    if (sm < 1) sm = 1;
    int bps = (occ < 4) ? occ : 4;
    if (bps < 1) bps = 1;
    int grid = sm * bps;

    k_fused<<<grid, 256>>>(v_input, target, W1, W2, Wfb, gain1, gain2, out);
    (void)in_sizes; (void)n_in; (void)out_size;
}

// round 17
// speedup vs baseline: 1.0336x; 1.0004x over previous
#include <cuda_runtime.h>
#include <math.h>

// Problem constants
#define HH     8192
#define IDIM   4096
#define ODIM   4096
#define NTOT   (HH + ODIM)      // 12288
#define NSTEPS 100
#define MAXROWS 64              // max rows any block can own (grid >= 152)

// Scratch (no allocations allowed)
__device__ __align__(128) float g_Ihid[HH];   // compress(W1 @ v_input)
__device__ __align__(128) float g_Iout[ODIM]; // compress(W2 @ I_hidden)

// Grid barrier state (sense-reversal; safe across graph replays).
__device__ unsigned g_bar_cnt = 0;
__device__ volatile unsigned g_bar_gen = 0;

__device__ __forceinline__ void grid_barrier() {
    __syncthreads();
    if (threadIdx.x == 0) {
        unsigned gen = g_bar_gen;           // read phase BEFORE arriving
        __threadfence();                    // publish this block's writes
        if (atomicAdd(&g_bar_cnt, 1u) == gridDim.x - 1u) {
            g_bar_cnt = 0;
            __threadfence();
            g_bar_gen = gen + 1u;           // release
        } else {
            while (g_bar_gen == gen) { }
        }
    }
    __syncthreads();
}

__device__ __forceinline__ float compress_fn(float x, float gain) {
    float s = (x > 0.0f) ? 1.0f : ((x < 0.0f) ? -1.0f : 0.0f);
    return s * log1pf(gain * fabsf(x) + 1e-6f);
}

__device__ __forceinline__ int range_pt(int b, int G, int R) {
    return (int)(((long long)b * R) / G);
}

__device__ __forceinline__ unsigned smem_addr_u32(const void* p) {
    return (unsigned)__cvta_generic_to_shared(p);
}

// 4-row dot via cp.async double-buffered staging. Chunk c = 256 float4 per
// row = iteration k=c of the R13 loop: thread t consumes idx c*256+t with
// FMAs in .x.y.z.w order per row, rows 0..3 — BIT-IDENTICAL numerics.
// Each thread reads back only the float4 it staged itself, so completion is
// per-thread (cp.async.wait_group); no block barrier anywhere in the loop.
template <int NCOLS>
__device__ __forceinline__ void rows4_dot_async(
    const float* __restrict__ W, const float* __restrict__ x, int row0,
    float4 (*sbuf)[4][256],     // [2][4][256] double buffer
    float& a0, float& a1, float& a2, float& a3)
{
    constexpr int NCH = NCOLS / 1024;           // 1KB-per-row chunks
    constexpr size_t RS = (size_t)NCOLS * 4;    // row stride bytes
    const int t = threadIdx.x;
    const float4* xv = reinterpret_cast<const float4*>(x);
    const char* wbase = reinterpret_cast<const char*>(W) + (size_t)row0 * RS;
    unsigned sb = smem_addr_u32(&sbuf[0][0][0]);

    // Prologue: stage chunk 0 into buffer 0.
    {
        const char* g = wbase + (size_t)t * 16;
        #pragma unroll
        for (int r = 0; r < 4; ++r)
            asm volatile("cp.async.cg.shared.global [%0], [%1], 16;" ::
                "r"(sb + (unsigned)((r * 256 + t) * 16)), "l"(g + (size_t)r * RS)
                : "memory");
        asm volatile("cp.async.commit_group;" ::: "memory");
    }

    a0 = a1 = a2 = a3 = 0.0f;
    #pragma unroll
    for (int c = 0; c < NCH; ++c) {
        if (c + 1 < NCH) {
            unsigned d = sb + (unsigned)(((((c + 1) & 1) * 4) * 256 + t) * 16);
            const char* g = wbase + ((size_t)(c + 1) * 256 + t) * 16;
            #pragma unroll
            for (int r = 0; r < 4; ++r)
                asm volatile("cp.async.cg.shared.global [%0], [%1], 16;" ::
                    "r"(d + (unsigned)(r * 256 * 16)), "l"(g + (size_t)r * RS)
                    : "memory");
            asm volatile("cp.async.commit_group;" ::: "memory");
            asm volatile("cp.async.wait_group 1;" ::: "memory");
        } else {
            asm volatile("cp.async.wait_group 0;" ::: "memory");
        }
        float4 xx = xv[c * 256 + t];
        float4 r0 = sbuf[c & 1][0][t];
        float4 r1 = sbuf[c & 1][1][t];
        float4 r2 = sbuf[c & 1][2][t];
        float4 r3 = sbuf[c & 1][3][t];
        a0 = fmaf(r0.x, xx.x, a0); a0 = fmaf(r0.y, xx.y, a0);
        a0 = fmaf(r0.z, xx.z, a0); a0 = fmaf(r0.w, xx.w, a0);
        a1 = fmaf(r1.x, xx.x, a1); a1 = fmaf(r1.y, xx.y, a1);
        a1 = fmaf(r1.z, xx.z, a1); a1 = fmaf(r1.w, xx.w, a1);
        a2 = fmaf(r2.x, xx.x, a2); a2 = fmaf(r2.y, xx.y, a2);
        a2 = fmaf(r2.z, xx.z, a2); a2 = fmaf(r2.w, xx.w, a2);
        a3 = fmaf(r3.x, xx.x, a3); a3 = fmaf(r3.y, xx.y, a3);
        a3 = fmaf(r3.z, xx.z, a3); a3 = fmaf(r3.w, xx.w, a3);
    }
}

// Single-row dot, same per-thread/index ordering as all passing kernels.
template <int NCOLS>
__device__ __forceinline__ float row1_dot(const float* __restrict__ W,
                                          const float* __restrict__ x, int row) {
    const float4* xv = reinterpret_cast<const float4*>(x);
    const float4* wr = reinterpret_cast<const float4*>(W + (size_t)row * NCOLS);
    constexpr int PER = NCOLS / 4 / 256;
    float a = 0.0f;
    #pragma unroll
    for (int k = 0; k < PER; ++k) {
        int idx = k * 256 + threadIdx.x;
        float4 xx = xv[idx];
        float4 ww = wr[idx];
        a = fmaf(ww.x, xx.x, a); a = fmaf(ww.y, xx.y, a);
        a = fmaf(ww.z, xx.z, a); a = fmaf(ww.w, xx.w, a);
    }
    return a;
}

// Block reduce of 4 sums, 256 threads. Same xor tree as passing kernels.
__device__ __forceinline__ void block_reduce4(float& a0, float& a1, float& a2, float& a3) {
    __shared__ float s[8][4];
    __syncthreads();
    #pragma unroll
    for (int o = 16; o > 0; o >>= 1) {
        a0 += __shfl_xor_sync(0xffffffffu, a0, o);
        a1 += __shfl_xor_sync(0xffffffffu, a1, o);
        a2 += __shfl_xor_sync(0xffffffffu, a2, o);
        a3 += __shfl_xor_sync(0xffffffffu, a3, o);
    }
    if ((threadIdx.x & 31) == 0) {
        int w = threadIdx.x >> 5;
        s[w][0] = a0; s[w][1] = a1; s[w][2] = a2; s[w][3] = a3;
    }
    __syncthreads();
    if (threadIdx.x < 32) {
        bool in = threadIdx.x < 8;
        a0 = in ? s[threadIdx.x][0] : 0.0f;
        a1 = in ? s[threadIdx.x][1] : 0.0f;
        a2 = in ? s[threadIdx.x][2] : 0.0f;
        a3 = in ? s[threadIdx.x][3] : 0.0f;
        #pragma unroll
        for (int o = 4; o > 0; o >>= 1) {
            a0 += __shfl_xor_sync(0xffffffffu, a0, o);
            a1 += __shfl_xor_sync(0xffffffffu, a1, o);
            a2 += __shfl_xor_sync(0xffffffffu, a2, o);
            a3 += __shfl_xor_sync(0xffffffffu, a3, o);
        }
    }
}

// Block reduce of 1 sum (identical to R7's proven tree).
__device__ __forceinline__ float block_reduce1(float val) {
    __shared__ float s1[8];
    __syncthreads();
    #pragma unroll
    for (int o = 16; o > 0; o >>= 1)
        val += __shfl_xor_sync(0xffffffffu, val, o);
    if ((threadIdx.x & 31) == 0) s1[threadIdx.x >> 5] = val;
    __syncthreads();
    if (threadIdx.x < 32) {
        val = (threadIdx.x < 8) ? s1[threadIdx.x] : 0.0f;
        #pragma unroll
        for (int o = 4; o > 0; o >>= 1)
            val += __shfl_xor_sync(0xffffffffu, val, o);
    }
    return val;
}

// 100-step Izhikevich trajectory for one neuron.
// Output layout: out[0]=loss, v at out[1 + t*NTOT + n], u after all v.
__device__ __forceinline__ void izhi_run(int n, float Iin, float* __restrict__ out) {
    float* vp = out + 1 + n;
    float* up = out + 1 + (size_t)NSTEPS * NTOT + n;
    float v = -65.0f;
    float u = 0.2f * -65.0f;   // -13
    *vp = v; *up = u;
    #pragma unroll 4
    for (int t = 1; t < NSTEPS; ++t) {
        vp += NTOT; up += NTOT;
        float vn = v + (0.04f * v * v + 5.0f * v + 0.14f - u + Iin);
        float un = u + 0.02f * (0.2f * v - u);
        bool sp = (vn >= 30.0f);
        v = sp ? -65.0f : vn;
        u = sp ? (un + 8.0f) : un;
        *vp = v; *up = u;
    }
}

// Persistent kernel, all blocks co-resident. Static contiguous row ranges.
// Structure identical to R13; only the weight-load path changed to cp.async.
__global__ void __launch_bounds__(256, 4) k_fused(
    const float* __restrict__ vin,   const float* __restrict__ target,
    const float* __restrict__ W1,    const float* __restrict__ W2,
    const float* __restrict__ Wfb,   const float* __restrict__ gain1,
    const float* __restrict__ gain2, float* __restrict__ out)
{
    const int G = gridDim.x;
    const int b = blockIdx.x;
    __shared__ float4 sbuf[2][4][256];   // 32 KB staging (double buffer)

    // ---- Phase 1: g_Ihid = compress(W1 @ v_input, gain1) ----
    {
        int r0 = range_pt(b, G, HH), r1 = range_pt(b + 1, G, HH);
        int r = r0;
        for (; r + 4 <= r1; r += 4) {
            float a0, a1, a2, a3;
            rows4_dot_async<IDIM>(W1, vin, r, sbuf, a0, a1, a2, a3);
            block_reduce4(a0, a1, a2, a3);
            if (threadIdx.x == 0) {
                float gn = gain1[0];
                g_Ihid[r + 0] = compress_fn(a0, gn);
                g_Ihid[r + 1] = compress_fn(a1, gn);
                g_Ihid[r + 2] = compress_fn(a2, gn);
                g_Ihid[r + 3] = compress_fn(a3, gn);
            }
        }
        for (; r < r1; ++r) {
            float a = row1_dot<IDIM>(W1, vin, r);
            a = block_reduce1(a);
            if (threadIdx.x == 0)
                g_Ihid[r] = compress_fn(a, gain1[0]);
        }
    }
    grid_barrier();

    // ---- Phase 2: g_Iout = compress(W2 @ g_Ihid, gain2) ----
    {
        int r0 = range_pt(b, G, ODIM), r1 = range_pt(b + 1, G, ODIM);
        int r = r0;
        for (; r + 4 <= r1; r += 4) {
            float a0, a1, a2, a3;
            rows4_dot_async<HH>(W2, g_Ihid, r, sbuf, a0, a1, a2, a3);
            block_reduce4(a0, a1, a2, a3);
            if (threadIdx.x == 0) {
                float gn = gain2[0];
                g_Iout[r + 0] = compress_fn(a0, gn);
                g_Iout[r + 1] = compress_fn(a1, gn);
                g_Iout[r + 2] = compress_fn(a2, gn);
                g_Iout[r + 3] = compress_fn(a3, gn);
            }
        }
        for (; r < r1; ++r) {
            float a = row1_dot<HH>(W2, g_Ihid, r);
            a = block_reduce1(a);
            if (threadIdx.x == 0)
                g_Iout[r] = compress_fn(a, gain2[0]);
        }
    }
    grid_barrier();

    // ---- Phase 3: total_hidden = g_Ihid - Wfb @ g_Iout (currents kept in
    //      smem), then in-block hidden izhi; blocks 0..15 add output izhi,
    //      block 16 the loss. No further barriers. ----
    __shared__ float cur[MAXROWS];
    {
        int r0 = range_pt(b, G, HH), r1 = range_pt(b + 1, G, HH);
        int r = r0;
        for (; r + 4 <= r1; r += 4) {
            float a0, a1, a2, a3;
            rows4_dot_async<ODIM>(Wfb, g_Iout, r, sbuf, a0, a1, a2, a3);
            block_reduce4(a0, a1, a2, a3);
            if (threadIdx.x == 0) {
                int j = r - r0;
                cur[j + 0] = g_Ihid[r + 0] - a0;
                cur[j + 1] = g_Ihid[r + 1] - a1;
                cur[j + 2] = g_Ihid[r + 2] - a2;
                cur[j + 3] = g_Ihid[r + 3] - a3;
            }
        }
        for (; r < r1; ++r) {
            float a = row1_dot<ODIM>(Wfb, g_Iout, r);
            a = block_reduce1(a);
            if (threadIdx.x == 0)
                cur[r - r0] = g_Ihid[r] - a;
        }
        __syncthreads();

        // Hidden-neuron izhi for this block's own rows (contiguous lanes).
        int nrows = r1 - r0;
        if (threadIdx.x < nrows)
            izhi_run(r0 + threadIdx.x, cur[threadIdx.x], out);
    }

    // Output-neuron izhi: 16 blocks x 256 neurons (needs only g_Iout,
    // finalized at barrier 2).
    if (b < ODIM / 256) {
        int n = b * 256 + threadIdx.x;
        izhi_run(HH + n, g_Iout[n], out);
    } else if (b == ODIM / 256) {
        // loss = mean((I_output - target)^2)
        float acc = 0.0f;
        for (int i = threadIdx.x; i < ODIM; i += 256) {
            float d = g_Iout[i] - target[i];
            acc = fmaf(d, d, acc);
        }
        acc = block_reduce1(acc);
        if (threadIdx.x == 0)
            out[0] = acc / (float)ODIM;
    }
}

extern "C" void kernel_launch(void* const* d_in, const int* in_sizes, int n_in,
                              void* d_out, int out_size) {
    // metadata order: v_input, target_output, W1, W2, W_feedback, gain1, gain2
    const float* v_input = (const float*)d_in[0];
    const float* target  = (const float*)d_in[1];
    const float* W1      = (const float*)d_in[2];
    const float* W2      = (const float*)d_in[3];
    const float* Wfb     = (const float*)d_in[4];
    const float* gain1   = (const float*)d_in[5];
    const float* gain2   = (const float*)d_in[6];
    float* out = (float*)d_out;

    // Co-resident grid (spin barrier must not deadlock): min(occupancy, 4).
    int dev = 0;
    cudaGetDevice(&dev);
    int sm = 0;
    cudaDeviceGetAttribute(&sm, cudaDevAttrMultiProcessorCount, dev);
    int occ = 0;
    cudaOccupancyMaxActiveBlocksPerMultiprocessor(&occ, k_fused, 256, 0);
    if (sm < 1) sm = 1;
    int bps = (occ < 4) ? occ : 4;
    if (bps < 1) bps = 1;
    int grid = sm * bps;

    k_fused<<<grid, 256>>>(v_input, target, W1, W2, Wfb, gain1, gain2, out);
    (void)in_sizes; (void)n_in; (void)out_size;
}